// round 15
// baseline (speedup 1.0000x reference)
#include <cuda_runtime.h>
#include <cuda_fp16.h>
#include <math.h>
#include <stdint.h>

#define B_  4
#define S_  2048
#define D_  1024
#define H_  16
#define DK_ 64
#define M_  (B_ * S_)

// ---------------------------------------------------------------------------
// Device-global scratch
// ---------------------------------------------------------------------------
__device__ float g_cos[S_ * 32];
__device__ float g_sin[S_ * 32];

__device__ __half g_xh[(size_t)M_ * D_];              // x single fp16
__device__ __half g_w[4][(size_t)D_ * D_];            // q,k,v,o single fp16
__device__ __half g_oh[(size_t)M_ * D_];              // O single fp16

// Q: single fp16 (pre-scaled 1/8 * log2e). K,V: single fp16.
__device__ __half g_Qh[(size_t)B_ * H_ * S_ * DK_];
__device__ __half g_Kh[(size_t)B_ * H_ * S_ * DK_];
__device__ __half g_Vh[(size_t)B_ * H_ * S_ * DK_];

// ---------------------------------------------------------------------------
// PTX helpers
// ---------------------------------------------------------------------------
__device__ __forceinline__ uint32_t smem_u32(const void* p) {
    uint32_t a;
    asm("{ .reg .u64 t; cvta.to.shared.u64 t, %1; cvt.u32.u64 %0, t; }"
        : "=r"(a) : "l"(p));
    return a;
}
__device__ __forceinline__ void ldsm_x4(uint32_t* r, uint32_t addr) {
    asm volatile("ldmatrix.sync.aligned.m8n8.x4.shared.b16 {%0,%1,%2,%3}, [%4];"
                 : "=r"(r[0]), "=r"(r[1]), "=r"(r[2]), "=r"(r[3]) : "r"(addr));
}
__device__ __forceinline__ void ldsm_x4_t(uint32_t* r, uint32_t addr) {
    asm volatile("ldmatrix.sync.aligned.m8n8.x4.trans.shared.b16 {%0,%1,%2,%3}, [%4];"
                 : "=r"(r[0]), "=r"(r[1]), "=r"(r[2]), "=r"(r[3]) : "r"(addr));
}
__device__ __forceinline__ void mma_f16(float* d, const uint32_t* a,
                                        const uint32_t* b) {
    asm volatile(
        "mma.sync.aligned.m16n8k16.row.col.f32.f16.f16.f32 "
        "{%0,%1,%2,%3}, {%4,%5,%6,%7}, {%8,%9}, {%0,%1,%2,%3};"
        : "+f"(d[0]), "+f"(d[1]), "+f"(d[2]), "+f"(d[3])
        : "r"(a[0]), "r"(a[1]), "r"(a[2]), "r"(a[3]), "r"(b[0]), "r"(b[1]));
}
__device__ __forceinline__ void cp16(uint32_t dst, const void* src) {
    asm volatile("cp.async.cg.shared.global [%0], [%1], 16;"
                 :: "r"(dst), "l"(src) : "memory");
}
#define CP_COMMIT() asm volatile("cp.async.commit_group;" ::: "memory")
#define CP_WAIT0()  asm volatile("cp.async.wait_group 0;" ::: "memory")
#define CP_WAIT1()  asm volatile("cp.async.wait_group 1;" ::: "memory")
#define CP_WAIT2()  asm volatile("cp.async.wait_group 2;" ::: "memory")

__device__ __forceinline__ uint32_t pack_f2(float a, float b) {
    __half2 v = __float22half2_rn(make_float2(a, b));
    return *(uint32_t*)&v;
}

// ---------------------------------------------------------------------------
// RoPE table
// ---------------------------------------------------------------------------
__global__ void rope_table_kernel(const int* __restrict__ pos) {
    int idx = blockIdx.x * blockDim.x + threadIdx.x;
    if (idx >= S_ * 32) return;
    int s = idx >> 5;
    int p = idx & 31;
    float inv_freq = (float)pow(10000.0, -((double)(2 * p)) / 64.0);
    float ang = (float)pos[s] * inv_freq;
    g_cos[idx] = (float)cos((double)ang);
    g_sin[idx] = (float)sin((double)ang);
}

// ---------------------------------------------------------------------------
// Fused converts: x -> single fp16, weights -> single fp16.
// ---------------------------------------------------------------------------
__global__ void convert_all_kernel(const float* __restrict__ x,
                                   const float* __restrict__ wq,
                                   const float* __restrict__ wk,
                                   const float* __restrict__ wv,
                                   const float* __restrict__ wo) {
    int i = blockIdx.x * blockDim.x + threadIdx.x;
    if (i >= 2097152 + 4 * 262144) return;
    const float* src;
    __half* dst;
    int off;
    if (i < 2097152) {
        src = x; dst = g_xh; off = i;
    } else {
        int j = i - 2097152;
        int wsel = j >> 18;
        off = j & 262143;
        src = (wsel == 0) ? wq : (wsel == 1) ? wk : (wsel == 2) ? wv : wo;
        dst = g_w[wsel];
    }
    float4 v = ((const float4*)src)[off];
    ((uint32_t*)dst)[2 * off]     = pack_f2(v.x, v.y);
    ((uint32_t*)dst)[2 * off + 1] = pack_f2(v.z, v.w);
}

// ---------------------------------------------------------------------------
// Big-tile GEMM geometry: CTA 256x128, BK=64, 8 warps (4x2), warp 64x64.
// Stage: A 256x64 fp16 (36864 B) + B 128x64 (18432 B) = 55296 B; 3 stages.
// ---------------------------------------------------------------------------
#define T_STRIDE 144
#define BG_A_BYTES (256 * T_STRIDE)       // 36864
#define BG_B_BYTES (128 * T_STRIDE)       // 18432
#define BG_STAGE   (BG_A_BYTES + BG_B_BYTES)   // 55296
#define BG_SMEM    (3 * BG_STAGE)         // 165888

// ZMODE: 0,1,2 -> QKV epilogues; 3 -> output projection (fp32 store)
template <int ZSEL>
__global__ void __launch_bounds__(256, 1) big_gemm_kernel(float* __restrict__ Cout) {
    extern __shared__ char sm[];
    const int tid  = threadIdx.x;
    const int w    = tid >> 5;
    const int lane = tid & 31;
    const int wm   = w >> 1;            // 0..3 -> 64 rows each
    const int wn   = w & 1;             // 0..1 -> 64 cols each
    const int n0   = blockIdx.x * 128;
    const int m0   = blockIdx.y * 256;
    const int z    = (ZSEL == 4) ? (int)blockIdx.z : ZSEL;

    const uint32_t sbase = smem_u32(sm);

    const __half* srcA = ((ZSEL == 3) ? g_oh : g_xh) + (size_t)m0 * D_;
    const __half* srcB = g_w[(ZSEL == 3) ? 3 : 0] + (size_t)n0 * D_;
    if (ZSEL == 4) srcB = g_w[z] + (size_t)n0 * D_;

    auto load_stage = [&](int kt, int st) {
        uint32_t sb = sbase + st * BG_STAGE;
#pragma unroll
        for (int u = 0; u < 8; ++u) {       // A: rows 0..255
            int f = tid + u * 256;
            int r = f >> 3;
            int c = f & 7;
            cp16(sb + r * T_STRIDE + c * 16,
                 srcA + (size_t)r * D_ + kt * 64 + c * 8);
        }
#pragma unroll
        for (int u = 0; u < 4; ++u) {       // B: rows 0..127
            int f = tid + u * 256;
            int r = f >> 3;
            int c = f & 7;
            cp16(sb + BG_A_BYTES + r * T_STRIDE + c * 16,
                 srcB + (size_t)r * D_ + kt * 64 + c * 8);
        }
    };

    float d[4][8][4];
#pragma unroll
    for (int i = 0; i < 4; ++i)
#pragma unroll
        for (int j = 0; j < 8; ++j)
#pragma unroll
            for (int q = 0; q < 4; ++q) d[i][j][q] = 0.f;

    load_stage(0, 0); CP_COMMIT();
    load_stage(1, 1); CP_COMMIT();

    int st = 0;
    for (int kt = 0; kt < 16; ++kt) {
        if (kt + 2 < 16) {
            load_stage(kt + 2, (st + 2) % 3);
            CP_COMMIT();
            CP_WAIT2();
        } else if (kt + 1 < 16) {
            CP_WAIT1();
        } else {
            CP_WAIT0();
        }
        __syncthreads();

        const uint32_t oA0 = sbase + st * BG_STAGE;
        const uint32_t oB0 = oA0 + BG_A_BYTES;

#pragma unroll
        for (int ks = 0; ks < 4; ++ks) {
            const int k0 = ks * 16;
            uint32_t ah[4][4];
            {
                int arow = wm * 64 + (lane & 15);
                int acol = 2 * k0 + (lane >> 4) * 16;
#pragma unroll
                for (int i = 0; i < 4; ++i) {
                    uint32_t off = (uint32_t)((arow + i * 16) * T_STRIDE + acol);
                    ldsm_x4(ah[i], oA0 + off);
                }
            }
            uint32_t bh[8][2];
            {
                int brow_l = (lane & 7) + ((lane >> 4) & 1) * 8;
                int bcol   = 2 * k0 + ((lane >> 3) & 1) * 16;
#pragma unroll
                for (int g = 0; g < 4; ++g) {
                    uint32_t off = (uint32_t)((wn * 64 + g * 16 + brow_l) * T_STRIDE + bcol);
                    uint32_t r4[4];
                    ldsm_x4(r4, oB0 + off);
                    bh[2 * g][0] = r4[0]; bh[2 * g][1] = r4[1];
                    bh[2 * g + 1][0] = r4[2]; bh[2 * g + 1][1] = r4[3];
                }
            }
#pragma unroll
            for (int i = 0; i < 4; ++i)
#pragma unroll
                for (int j = 0; j < 8; ++j)
                    mma_f16(d[i][j], ah[i], bh[j]);
        }
        __syncthreads();
        st = (st + 1) % 3;
    }

    // Epilogue
    const float qscale = 0.125f * 1.44269504f;   // 1/sqrt(dk) * log2(e)
#pragma unroll
    for (int i = 0; i < 4; ++i) {
        int mrow = m0 + wm * 64 + i * 16 + (lane >> 2);
#pragma unroll
        for (int half = 0; half < 2; ++half) {
            int m = mrow + half * 8;
            int b = m >> 11;
            int s = m & (S_ - 1);
#pragma unroll
            for (int j = 0; j < 8; ++j) {
                int n = n0 + wn * 64 + j * 8 + 2 * (lane & 3);
                float x0 = d[i][j][2 * half];
                float x1 = d[i][j][2 * half + 1];
                if (ZSEL == 3) {
                    *(float2*)(Cout + (size_t)m * D_ + n) = make_float2(x0, x1);
                } else {
                    int h = n >> 6;
                    int dk = n & 63;
                    float y0, y1;
                    if (z != 2) {
                        int p = dk >> 1;
                        float c = g_cos[s * 32 + p];
                        float sn = g_sin[s * 32 + p];
                        y0 = c * x0 - sn * x1;
                        y1 = sn * x0 + c * x1;
                    } else {
                        y0 = x0; y1 = x1;
                    }
                    if (z == 0) { y0 *= qscale; y1 *= qscale; }
                    size_t idx = (((size_t)(b * H_ + h) * S_ + s) * DK_ + dk);
                    uint32_t pk = pack_f2(y0, y1);
                    if (z == 0)      *(uint32_t*)(g_Qh + idx) = pk;
                    else if (z == 1) *(uint32_t*)(g_Kh + idx) = pk;
                    else             *(uint32_t*)(g_Vh + idx) = pk;
                }
            }
        }
    }
}

// ---------------------------------------------------------------------------
// Tensor-core flash attention (causal, fp16, exp2-domain softmax):
// 128-key load stages, processed as two 64-key halves.  (unchanged from R14)
// ---------------------------------------------------------------------------
#define AK_TILE (128 * 144)               // 18432 (128 rows)
#define A_STAGE (2 * AK_TILE)             // 36864 (K128, V128)
#define ATT_SMEM (2 * A_STAGE)            // 73728

__global__ void __launch_bounds__(256, 2) attn_mma_kernel() {
    extern __shared__ char asm_[];
    const int qb = gridDim.x - 1 - blockIdx.x;
    const int bh = blockIdx.y;
    const int tid = threadIdx.x;
    const int w = tid >> 5;
    const int lane = tid & 31;
    const int q0w = qb * 128 + w * 16;
    const size_t hb = (size_t)bh * S_ * DK_;

    const uint32_t sbase = smem_u32(asm_);

    const __half* srcs[2] = { g_Kh + hb, g_Vh + hb };

    auto load_stage = [&](int kt, int st) {
        uint32_t sb = sbase + st * A_STAGE;
        const size_t roff = (size_t)(kt * 128) * 64;
#pragma unroll
        for (int t = 0; t < 2; ++t) {
#pragma unroll
            for (int u = 0; u < 4; ++u) {
                int f = tid + u * 256;
                int r = f >> 3;
                int c = f & 7;
                cp16(sb + t * AK_TILE + r * 144 + c * 16,
                     srcs[t] + roff + (size_t)r * 64 + c * 8);
            }
        }
    };

    uint32_t qh[4][4];
    {
        const int r0 = q0w + (lane >> 2);
        const int c2 = (lane & 3) * 2;
        const __half* Qh = g_Qh + hb;
#pragma unroll
        for (int t = 0; t < 4; ++t) {
            qh[t][0] = *(const uint32_t*)(Qh + (size_t)r0 * 64 + t * 16 + c2);
            qh[t][1] = *(const uint32_t*)(Qh + (size_t)(r0 + 8) * 64 + t * 16 + c2);
            qh[t][2] = *(const uint32_t*)(Qh + (size_t)r0 * 64 + t * 16 + 8 + c2);
            qh[t][3] = *(const uint32_t*)(Qh + (size_t)(r0 + 8) * 64 + t * 16 + 8 + c2);
        }
    }

    float o[8][4];
#pragma unroll
    for (int j = 0; j < 8; ++j)
#pragma unroll
        for (int q = 0; q < 4; ++q) o[j][q] = 0.f;
    float m0 = -3.0e38f, m1 = -3.0e38f, l0 = 0.f, l1 = 0.f;

    const int nkt = qb + 1;
    load_stage(0, 0);
    CP_COMMIT();

    for (int kt = 0; kt < nkt; ++kt) {
        const int st = kt & 1;
        if (kt + 1 < nkt) {
            load_stage(kt + 1, st ^ 1);
            CP_COMMIT();
            CP_WAIT1();
        } else {
            CP_WAIT0();
        }
        __syncthreads();

#pragma unroll
        for (int hh = 0; hh < 2; ++hh) {
            const int k0 = kt * 128 + hh * 64;
            if (q0w + 15 < k0) break;

            const uint32_t sKh = sbase + st * A_STAGE + hh * (64 * 144);
            const uint32_t sVh = sbase + st * A_STAGE + AK_TILE + hh * (64 * 144);

            float s[8][4];
#pragma unroll
            for (int j = 0; j < 8; ++j)
#pragma unroll
                for (int q = 0; q < 4; ++q) s[j][q] = 0.f;

            const int brow = (lane & 7) + ((lane >> 4) & 1) * 8;
#pragma unroll
            for (int t = 0; t < 4; ++t) {
                uint32_t kh[8][2];
                int bcol = t * 32 + ((lane >> 3) & 1) * 16;
#pragma unroll
                for (int g = 0; g < 4; ++g) {
                    uint32_t off = (uint32_t)((g * 16 + brow) * 144 + bcol);
                    uint32_t r4[4];
                    ldsm_x4(r4, sKh + off);
                    kh[2 * g][0] = r4[0]; kh[2 * g][1] = r4[1];
                    kh[2 * g + 1][0] = r4[2]; kh[2 * g + 1][1] = r4[3];
                }
#pragma unroll
                for (int j = 0; j < 8; ++j)
                    mma_f16(s[j], qh[t], kh[j]);
            }

            const int r0 = q0w + (lane >> 2);
            if (k0 + 63 > q0w) {
#pragma unroll
                for (int j = 0; j < 8; ++j) {
                    int col = k0 + 8 * j + 2 * (lane & 3);
                    if (col > r0)         s[j][0] = -3.0e38f;
                    if (col + 1 > r0)     s[j][1] = -3.0e38f;
                    if (col > r0 + 8)     s[j][2] = -3.0e38f;
                    if (col + 1 > r0 + 8) s[j][3] = -3.0e38f;
                }
            }

            float mx0 = -3.0e38f, mx1 = -3.0e38f;
#pragma unroll
            for (int j = 0; j < 8; ++j) {
                mx0 = fmaxf(mx0, fmaxf(s[j][0], s[j][1]));
                mx1 = fmaxf(mx1, fmaxf(s[j][2], s[j][3]));
            }
            mx0 = fmaxf(mx0, __shfl_xor_sync(0xffffffffu, mx0, 1));
            mx0 = fmaxf(mx0, __shfl_xor_sync(0xffffffffu, mx0, 2));
            mx1 = fmaxf(mx1, __shfl_xor_sync(0xffffffffu, mx1, 1));
            mx1 = fmaxf(mx1, __shfl_xor_sync(0xffffffffu, mx1, 2));
            float mn0 = fmaxf(m0, mx0), mn1 = fmaxf(m1, mx1);
            float a0 = exp2f(m0 - mn0), a1 = exp2f(m1 - mn1);

            uint32_t Ph[8][2];
            float sum0 = 0.f, sum1 = 0.f;
#pragma unroll
            for (int j = 0; j < 8; ++j) {
                float p0 = exp2f(s[j][0] - mn0);
                float p1 = exp2f(s[j][1] - mn0);
                float p2 = exp2f(s[j][2] - mn1);
                float p3 = exp2f(s[j][3] - mn1);
                sum0 += p0 + p1;
                sum1 += p2 + p3;
                Ph[j][0] = pack_f2(p0, p1);
                Ph[j][1] = pack_f2(p2, p3);
            }
            sum0 += __shfl_xor_sync(0xffffffffu, sum0, 1);
            sum0 += __shfl_xor_sync(0xffffffffu, sum0, 2);
            sum1 += __shfl_xor_sync(0xffffffffu, sum1, 1);
            sum1 += __shfl_xor_sync(0xffffffffu, sum1, 2);
            l0 = l0 * a0 + sum0;
            l1 = l1 * a1 + sum1;
            m0 = mn0; m1 = mn1;
#pragma unroll
            for (int j = 0; j < 8; ++j) {
                o[j][0] *= a0; o[j][1] *= a0; o[j][2] *= a1; o[j][3] *= a1;
            }

#pragma unroll
            for (int t = 0; t < 4; ++t) {
                uint32_t ap[4] = { Ph[2 * t][0], Ph[2 * t][1],
                                   Ph[2 * t + 1][0], Ph[2 * t + 1][1] };
                uint32_t vh[8][2];
                int vrow = t * 16 + (lane & 15);
#pragma unroll
                for (int g = 0; g < 4; ++g) {
                    uint32_t off = (uint32_t)(vrow * 144 + (g * 16 + (lane >> 4) * 8) * 2);
                    uint32_t r4[4];
                    ldsm_x4_t(r4, sVh + off);
                    vh[2 * g][0] = r4[0]; vh[2 * g][1] = r4[1];
                    vh[2 * g + 1][0] = r4[2]; vh[2 * g + 1][1] = r4[3];
                }
#pragma unroll
                for (int j = 0; j < 8; ++j)
                    mma_f16(o[j], ap, vh[j]);
            }
        }
        __syncthreads();
    }

    const float inv0 = 1.0f / l0, inv1 = 1.0f / l1;
    const int b = bh >> 4, h = bh & 15;
    const int s0 = q0w + (lane >> 2);
    const int c2 = 2 * (lane & 3);
#pragma unroll
    for (int j = 0; j < 8; ++j) {
        int dk = 8 * j + c2;
        {
            size_t idx = ((size_t)(b * S_) + s0) * D_ + h * 64 + dk;
            *(uint32_t*)(g_oh + idx) = pack_f2(o[j][0] * inv0, o[j][1] * inv0);
        }
        {
            size_t idx = ((size_t)(b * S_) + s0 + 8) * D_ + h * 64 + dk;
            *(uint32_t*)(g_oh + idx) = pack_f2(o[j][2] * inv1, o[j][3] * inv1);
        }
    }
}

// ---------------------------------------------------------------------------
// Launch
// ---------------------------------------------------------------------------
extern "C" void kernel_launch(void* const* d_in, const int* in_sizes, int n_in,
                              void* d_out, int out_size) {
    const float* x   = (const float*)d_in[0];
    const int*   pos = (const int*)d_in[1];
    const float* wq  = (const float*)d_in[2];
    const float* wk  = (const float*)d_in[3];
    const float* wv  = (const float*)d_in[4];
    const float* wo  = (const float*)d_in[5];
    float* out = (float*)d_out;
    (void)in_sizes; (void)n_in; (void)out_size;

    cudaFuncSetAttribute((const void*)big_gemm_kernel<4>,
                         cudaFuncAttributeMaxDynamicSharedMemorySize, BG_SMEM);
    cudaFuncSetAttribute((const void*)big_gemm_kernel<3>,
                         cudaFuncAttributeMaxDynamicSharedMemorySize, BG_SMEM);
    cudaFuncSetAttribute((const void*)attn_mma_kernel,
                         cudaFuncAttributeMaxDynamicSharedMemorySize, ATT_SMEM);

    // 1. RoPE tables
    rope_table_kernel<<<(S_ * 32 + 255) / 256, 256>>>(pos);

    // 2. Fused converts (x and weights -> single fp16)
    {
        int total = 2097152 + 4 * 262144;
        convert_all_kernel<<<(total + 255) / 256, 256>>>(x, wq, wk, wv, wo);
    }

    // 3. Fused QKV projection, 256x128 tiles (ZSEL=4 -> z from blockIdx.z)
    big_gemm_kernel<4><<<dim3(D_ / 128, M_ / 256, 3), 256, BG_SMEM>>>(nullptr);

    // 4. fp16 tensor-core causal flash attention -> g_oh
    attn_mma_kernel<<<dim3(S_ / 128, B_ * H_), 256, ATT_SMEM>>>();

    // 5. Output projection, 256x128 tiles -> d_out
    big_gemm_kernel<3><<<dim3(D_ / 128, M_ / 256), 256, BG_SMEM>>>(out);
}

// round 16
// speedup vs baseline: 1.1223x; 1.1223x over previous
#include <cuda_runtime.h>
#include <cuda_fp16.h>
#include <math.h>
#include <stdint.h>

#define B_  4
#define S_  2048
#define D_  1024
#define H_  16
#define DK_ 64
#define M_  (B_ * S_)

// ---------------------------------------------------------------------------
// Device-global scratch
// ---------------------------------------------------------------------------
__device__ float g_cos[S_ * 32];
__device__ float g_sin[S_ * 32];

__device__ __half g_xh[(size_t)M_ * D_];              // x single fp16
__device__ __half g_w[4][(size_t)D_ * D_];            // q,k,v,o single fp16
__device__ __half g_oh[(size_t)M_ * D_];              // O single fp16

// Q: single fp16 (pre-scaled 1/8 * log2e). K,V: single fp16.
__device__ __half g_Qh[(size_t)B_ * H_ * S_ * DK_];
__device__ __half g_Kh[(size_t)B_ * H_ * S_ * DK_];
__device__ __half g_Vh[(size_t)B_ * H_ * S_ * DK_];

// ---------------------------------------------------------------------------
// PTX helpers
// ---------------------------------------------------------------------------
__device__ __forceinline__ uint32_t smem_u32(const void* p) {
    uint32_t a;
    asm("{ .reg .u64 t; cvta.to.shared.u64 t, %1; cvt.u32.u64 %0, t; }"
        : "=r"(a) : "l"(p));
    return a;
}
__device__ __forceinline__ void ldsm_x4(uint32_t* r, uint32_t addr) {
    asm volatile("ldmatrix.sync.aligned.m8n8.x4.shared.b16 {%0,%1,%2,%3}, [%4];"
                 : "=r"(r[0]), "=r"(r[1]), "=r"(r[2]), "=r"(r[3]) : "r"(addr));
}
__device__ __forceinline__ void ldsm_x4_t(uint32_t* r, uint32_t addr) {
    asm volatile("ldmatrix.sync.aligned.m8n8.x4.trans.shared.b16 {%0,%1,%2,%3}, [%4];"
                 : "=r"(r[0]), "=r"(r[1]), "=r"(r[2]), "=r"(r[3]) : "r"(addr));
}
__device__ __forceinline__ void mma_f16(float* d, const uint32_t* a,
                                        const uint32_t* b) {
    asm volatile(
        "mma.sync.aligned.m16n8k16.row.col.f32.f16.f16.f32 "
        "{%0,%1,%2,%3}, {%4,%5,%6,%7}, {%8,%9}, {%0,%1,%2,%3};"
        : "+f"(d[0]), "+f"(d[1]), "+f"(d[2]), "+f"(d[3])
        : "r"(a[0]), "r"(a[1]), "r"(a[2]), "r"(a[3]), "r"(b[0]), "r"(b[1]));
}
__device__ __forceinline__ void cp16(uint32_t dst, const void* src) {
    asm volatile("cp.async.cg.shared.global [%0], [%1], 16;"
                 :: "r"(dst), "l"(src) : "memory");
}
#define CP_COMMIT() asm volatile("cp.async.commit_group;" ::: "memory")
#define CP_WAIT0()  asm volatile("cp.async.wait_group 0;" ::: "memory")
#define CP_WAIT1()  asm volatile("cp.async.wait_group 1;" ::: "memory")
#define CP_WAIT2()  asm volatile("cp.async.wait_group 2;" ::: "memory")

__device__ __forceinline__ uint32_t pack_f2(float a, float b) {
    __half2 v = __float22half2_rn(make_float2(a, b));
    return *(uint32_t*)&v;
}

// ---------------------------------------------------------------------------
// Fused setup: RoPE table + x/weight fp16 converts in one launch.
// Work items: [0, 65536) -> RoPE table entries (s*32+p)
//             [65536, 65536+3145728) -> float4 converts
// ---------------------------------------------------------------------------
#define N_ROPE   (S_ * 32)
#define N_CONV   (2097152 + 4 * 262144)

__global__ void setup_kernel(const int* __restrict__ pos,
                             const float* __restrict__ x,
                             const float* __restrict__ wq,
                             const float* __restrict__ wk,
                             const float* __restrict__ wv,
                             const float* __restrict__ wo) {
    int i = blockIdx.x * blockDim.x + threadIdx.x;
    if (i < N_ROPE) {
        int s = i >> 5;
        int p = i & 31;
        float inv_freq = (float)pow(10000.0, -((double)(2 * p)) / 64.0);
        float ang = (float)pos[s] * inv_freq;
        g_cos[i] = (float)cos((double)ang);
        g_sin[i] = (float)sin((double)ang);
        return;
    }
    int j = i - N_ROPE;
    if (j >= N_CONV) return;
    const float* src;
    __half* dst;
    int off;
    if (j < 2097152) {
        src = x; dst = g_xh; off = j;
    } else {
        int k = j - 2097152;
        int wsel = k >> 18;
        off = k & 262143;
        src = (wsel == 0) ? wq : (wsel == 1) ? wk : (wsel == 2) ? wv : wo;
        dst = g_w[wsel];
    }
    float4 v = ((const float4*)src)[off];
    ((uint32_t*)dst)[2 * off]     = pack_f2(v.x, v.y);
    ((uint32_t*)dst)[2 * off + 1] = pack_f2(v.z, v.w);
}

// ---------------------------------------------------------------------------
// Tile geometry shared by GEMMs (3-stage cp.async pipeline) — R14 config.
// ---------------------------------------------------------------------------
#define T_STRIDE 144
#define T_BYTES  (128 * T_STRIDE)        // 18432
#define G_STAGE  (2 * T_BYTES)           // 36864 (A, B)
#define GEMM_SMEM (3 * G_STAGE)          // 110592

// ---------------------------------------------------------------------------
// Fused QKV GEMM (fp16 single-term). Grid is x-major with z fastest:
// blockIdx.x encodes (n_tile * 3 + z) so the 3 weight streams share L2 windows.
// ---------------------------------------------------------------------------
__global__ void __launch_bounds__(256, 2) qkv_gemm_kernel() {
    extern __shared__ char sm[];
    const int tid  = threadIdx.x;
    const int w    = tid >> 5;
    const int lane = tid & 31;
    const int wm   = w >> 1;
    const int wn   = w & 1;
    const int z    = blockIdx.x % 3;
    const int n0   = (blockIdx.x / 3) * 128;
    const int m0   = blockIdx.y * 128;

    const uint32_t sbase = smem_u32(sm);

    const __half* srcs[2] = {
        g_xh + (size_t)m0 * D_, g_w[z] + (size_t)n0 * D_ };

    auto load_stage = [&](int kt, int st) {
        uint32_t sb = sbase + st * G_STAGE;
#pragma unroll
        for (int t = 0; t < 2; ++t) {
#pragma unroll
            for (int u = 0; u < 4; ++u) {
                int f = tid + u * 256;
                int r = f >> 3;
                int c = f & 7;
                cp16(sb + t * T_BYTES + r * T_STRIDE + c * 16,
                     srcs[t] + (size_t)r * D_ + kt * 64 + c * 8);
            }
        }
    };

    float d[2][8][4];
#pragma unroll
    for (int i = 0; i < 2; ++i)
#pragma unroll
        for (int j = 0; j < 8; ++j)
#pragma unroll
            for (int q = 0; q < 4; ++q) d[i][j][q] = 0.f;

    load_stage(0, 0); CP_COMMIT();
    load_stage(1, 1); CP_COMMIT();

    int st = 0;
    for (int kt = 0; kt < 16; ++kt) {
        if (kt + 2 < 16) {
            load_stage(kt + 2, (st + 2) % 3);
            CP_COMMIT();
            CP_WAIT2();
        } else if (kt + 1 < 16) {
            CP_WAIT1();
        } else {
            CP_WAIT0();
        }
        __syncthreads();

        const uint32_t oA0 = sbase + st * G_STAGE;
        const uint32_t oB0 = oA0 + T_BYTES;

#pragma unroll
        for (int ks = 0; ks < 4; ++ks) {
            const int k0 = ks * 16;
            uint32_t ah[2][4];
            {
                int arow = wm * 32 + (lane & 15);
                int acol = 2 * k0 + (lane >> 4) * 16;
#pragma unroll
                for (int i = 0; i < 2; ++i) {
                    uint32_t off = (uint32_t)((arow + i * 16) * T_STRIDE + acol);
                    ldsm_x4(ah[i], oA0 + off);
                }
            }
            uint32_t bh[8][2];
            {
                int brow_l = (lane & 7) + ((lane >> 4) & 1) * 8;
                int bcol   = 2 * k0 + ((lane >> 3) & 1) * 16;
#pragma unroll
                for (int g = 0; g < 4; ++g) {
                    uint32_t off = (uint32_t)((wn * 64 + g * 16 + brow_l) * T_STRIDE + bcol);
                    uint32_t r4[4];
                    ldsm_x4(r4, oB0 + off);
                    bh[2 * g][0] = r4[0]; bh[2 * g][1] = r4[1];
                    bh[2 * g + 1][0] = r4[2]; bh[2 * g + 1][1] = r4[3];
                }
            }
#pragma unroll
            for (int i = 0; i < 2; ++i)
#pragma unroll
                for (int j = 0; j < 8; ++j)
                    mma_f16(d[i][j], ah[i], bh[j]);
        }
        __syncthreads();
        st = (st + 1) % 3;
    }

    // Epilogue: RoPE (z<2) + scatter to [b,h,s,dk]
    const float qscale = 0.125f * 1.44269504f;   // 1/sqrt(dk) * log2(e)
#pragma unroll
    for (int i = 0; i < 2; ++i) {
        int mrow = m0 + wm * 32 + i * 16 + (lane >> 2);
#pragma unroll
        for (int half = 0; half < 2; ++half) {
            int m = mrow + half * 8;
            int b = m >> 11;
            int s = m & (S_ - 1);
#pragma unroll
            for (int j = 0; j < 8; ++j) {
                int n = n0 + wn * 64 + j * 8 + 2 * (lane & 3);
                float x0 = d[i][j][2 * half];
                float x1 = d[i][j][2 * half + 1];
                int h = n >> 6;
                int dk = n & 63;
                float y0, y1;
                if (z != 2) {
                    int p = dk >> 1;
                    float c = g_cos[s * 32 + p];
                    float sn = g_sin[s * 32 + p];
                    y0 = c * x0 - sn * x1;
                    y1 = sn * x0 + c * x1;
                } else {
                    y0 = x0; y1 = x1;
                }
                if (z == 0) { y0 *= qscale; y1 *= qscale; }
                size_t idx = (((size_t)(b * H_ + h) * S_ + s) * DK_ + dk);
                uint32_t pk = pack_f2(y0, y1);
                if (z == 0)      *(uint32_t*)(g_Qh + idx) = pk;
                else if (z == 1) *(uint32_t*)(g_Kh + idx) = pk;
                else             *(uint32_t*)(g_Vh + idx) = pk;
            }
        }
    }
}

// ---------------------------------------------------------------------------
// Output projection GEMM (fp16 single-term): out = O Wo^T, fp32 store.
// ---------------------------------------------------------------------------
__global__ void __launch_bounds__(256, 2) out_gemm_kernel(float* __restrict__ Cout) {
    extern __shared__ char sm[];
    const int tid  = threadIdx.x;
    const int w    = tid >> 5;
    const int lane = tid & 31;
    const int wm   = w >> 1;
    const int wn   = w & 1;
    const int n0   = blockIdx.x * 128;
    const int m0   = blockIdx.y * 128;

    const uint32_t sbase = smem_u32(sm);

    const __half* srcs[2] = {
        g_oh + (size_t)m0 * D_, g_w[3] + (size_t)n0 * D_ };

    auto load_stage = [&](int kt, int st) {
        uint32_t sb = sbase + st * G_STAGE;
#pragma unroll
        for (int t = 0; t < 2; ++t) {
#pragma unroll
            for (int u = 0; u < 4; ++u) {
                int f = tid + u * 256;
                int r = f >> 3;
                int c = f & 7;
                cp16(sb + t * T_BYTES + r * T_STRIDE + c * 16,
                     srcs[t] + (size_t)r * D_ + kt * 64 + c * 8);
            }
        }
    };

    float d[2][8][4];
#pragma unroll
    for (int i = 0; i < 2; ++i)
#pragma unroll
        for (int j = 0; j < 8; ++j)
#pragma unroll
            for (int q = 0; q < 4; ++q) d[i][j][q] = 0.f;

    load_stage(0, 0); CP_COMMIT();
    load_stage(1, 1); CP_COMMIT();

    int st = 0;
    for (int kt = 0; kt < 16; ++kt) {
        if (kt + 2 < 16) {
            load_stage(kt + 2, (st + 2) % 3);
            CP_COMMIT();
            CP_WAIT2();
        } else if (kt + 1 < 16) {
            CP_WAIT1();
        } else {
            CP_WAIT0();
        }
        __syncthreads();

        const uint32_t oA0 = sbase + st * G_STAGE;
        const uint32_t oB0 = oA0 + T_BYTES;

#pragma unroll
        for (int ks = 0; ks < 4; ++ks) {
            const int k0 = ks * 16;
            uint32_t ah[2][4];
            {
                int arow = wm * 32 + (lane & 15);
                int acol = 2 * k0 + (lane >> 4) * 16;
#pragma unroll
                for (int i = 0; i < 2; ++i) {
                    uint32_t off = (uint32_t)((arow + i * 16) * T_STRIDE + acol);
                    ldsm_x4(ah[i], oA0 + off);
                }
            }
            uint32_t bh[8][2];
            {
                int brow_l = (lane & 7) + ((lane >> 4) & 1) * 8;
                int bcol   = 2 * k0 + ((lane >> 3) & 1) * 16;
#pragma unroll
                for (int g = 0; g < 4; ++g) {
                    uint32_t off = (uint32_t)((wn * 64 + g * 16 + brow_l) * T_STRIDE + bcol);
                    uint32_t r4[4];
                    ldsm_x4(r4, oB0 + off);
                    bh[2 * g][0] = r4[0]; bh[2 * g][1] = r4[1];
                    bh[2 * g + 1][0] = r4[2]; bh[2 * g + 1][1] = r4[3];
                }
            }
#pragma unroll
            for (int i = 0; i < 2; ++i)
#pragma unroll
                for (int j = 0; j < 8; ++j)
                    mma_f16(d[i][j], ah[i], bh[j]);
        }
        __syncthreads();
        st = (st + 1) % 3;
    }

#pragma unroll
    for (int i = 0; i < 2; ++i) {
        int mrow = m0 + wm * 32 + i * 16 + (lane >> 2);
#pragma unroll
        for (int half = 0; half < 2; ++half) {
            int m = mrow + half * 8;
#pragma unroll
            for (int j = 0; j < 8; ++j) {
                int n = n0 + wn * 64 + j * 8 + 2 * (lane & 3);
                *(float2*)(Cout + (size_t)m * D_ + n) =
                    make_float2(d[i][j][2 * half], d[i][j][2 * half + 1]);
            }
        }
    }
}

// ---------------------------------------------------------------------------
// Tensor-core flash attention (causal, fp16, exp2-domain softmax):
// 128-key load stages, processed as two 64-key halves.  (unchanged from R14)
// ---------------------------------------------------------------------------
#define AK_TILE (128 * 144)               // 18432 (128 rows)
#define A_STAGE (2 * AK_TILE)             // 36864 (K128, V128)
#define ATT_SMEM (2 * A_STAGE)            // 73728

__global__ void __launch_bounds__(256, 2) attn_mma_kernel() {
    extern __shared__ char asm_[];
    const int qb = gridDim.x - 1 - blockIdx.x;
    const int bh = blockIdx.y;
    const int tid = threadIdx.x;
    const int w = tid >> 5;
    const int lane = tid & 31;
    const int q0w = qb * 128 + w * 16;
    const size_t hb = (size_t)bh * S_ * DK_;

    const uint32_t sbase = smem_u32(asm_);

    const __half* srcs[2] = { g_Kh + hb, g_Vh + hb };

    auto load_stage = [&](int kt, int st) {
        uint32_t sb = sbase + st * A_STAGE;
        const size_t roff = (size_t)(kt * 128) * 64;
#pragma unroll
        for (int t = 0; t < 2; ++t) {
#pragma unroll
            for (int u = 0; u < 4; ++u) {
                int f = tid + u * 256;
                int r = f >> 3;
                int c = f & 7;
                cp16(sb + t * AK_TILE + r * 144 + c * 16,
                     srcs[t] + roff + (size_t)r * 64 + c * 8);
            }
        }
    };

    uint32_t qh[4][4];
    {
        const int r0 = q0w + (lane >> 2);
        const int c2 = (lane & 3) * 2;
        const __half* Qh = g_Qh + hb;
#pragma unroll
        for (int t = 0; t < 4; ++t) {
            qh[t][0] = *(const uint32_t*)(Qh + (size_t)r0 * 64 + t * 16 + c2);
            qh[t][1] = *(const uint32_t*)(Qh + (size_t)(r0 + 8) * 64 + t * 16 + c2);
            qh[t][2] = *(const uint32_t*)(Qh + (size_t)r0 * 64 + t * 16 + 8 + c2);
            qh[t][3] = *(const uint32_t*)(Qh + (size_t)(r0 + 8) * 64 + t * 16 + 8 + c2);
        }
    }

    float o[8][4];
#pragma unroll
    for (int j = 0; j < 8; ++j)
#pragma unroll
        for (int q = 0; q < 4; ++q) o[j][q] = 0.f;
    float m0 = -3.0e38f, m1 = -3.0e38f, l0 = 0.f, l1 = 0.f;

    const int nkt = qb + 1;
    load_stage(0, 0);
    CP_COMMIT();

    for (int kt = 0; kt < nkt; ++kt) {
        const int st = kt & 1;
        if (kt + 1 < nkt) {
            load_stage(kt + 1, st ^ 1);
            CP_COMMIT();
            CP_WAIT1();
        } else {
            CP_WAIT0();
        }
        __syncthreads();

#pragma unroll
        for (int hh = 0; hh < 2; ++hh) {
            const int k0 = kt * 128 + hh * 64;
            if (q0w + 15 < k0) break;

            const uint32_t sKh = sbase + st * A_STAGE + hh * (64 * 144);
            const uint32_t sVh = sbase + st * A_STAGE + AK_TILE + hh * (64 * 144);

            float s[8][4];
#pragma unroll
            for (int j = 0; j < 8; ++j)
#pragma unroll
                for (int q = 0; q < 4; ++q) s[j][q] = 0.f;

            const int brow = (lane & 7) + ((lane >> 4) & 1) * 8;
#pragma unroll
            for (int t = 0; t < 4; ++t) {
                uint32_t kh[8][2];
                int bcol = t * 32 + ((lane >> 3) & 1) * 16;
#pragma unroll
                for (int g = 0; g < 4; ++g) {
                    uint32_t off = (uint32_t)((g * 16 + brow) * 144 + bcol);
                    uint32_t r4[4];
                    ldsm_x4(r4, sKh + off);
                    kh[2 * g][0] = r4[0]; kh[2 * g][1] = r4[1];
                    kh[2 * g + 1][0] = r4[2]; kh[2 * g + 1][1] = r4[3];
                }
#pragma unroll
                for (int j = 0; j < 8; ++j)
                    mma_f16(s[j], qh[t], kh[j]);
            }

            const int r0 = q0w + (lane >> 2);
            if (k0 + 63 > q0w) {
#pragma unroll
                for (int j = 0; j < 8; ++j) {
                    int col = k0 + 8 * j + 2 * (lane & 3);
                    if (col > r0)         s[j][0] = -3.0e38f;
                    if (col + 1 > r0)     s[j][1] = -3.0e38f;
                    if (col > r0 + 8)     s[j][2] = -3.0e38f;
                    if (col + 1 > r0 + 8) s[j][3] = -3.0e38f;
                }
            }

            float mx0 = -3.0e38f, mx1 = -3.0e38f;
#pragma unroll
            for (int j = 0; j < 8; ++j) {
                mx0 = fmaxf(mx0, fmaxf(s[j][0], s[j][1]));
                mx1 = fmaxf(mx1, fmaxf(s[j][2], s[j][3]));
            }
            mx0 = fmaxf(mx0, __shfl_xor_sync(0xffffffffu, mx0, 1));
            mx0 = fmaxf(mx0, __shfl_xor_sync(0xffffffffu, mx0, 2));
            mx1 = fmaxf(mx1, __shfl_xor_sync(0xffffffffu, mx1, 1));
            mx1 = fmaxf(mx1, __shfl_xor_sync(0xffffffffu, mx1, 2));
            float mn0 = fmaxf(m0, mx0), mn1 = fmaxf(m1, mx1);
            float a0 = exp2f(m0 - mn0), a1 = exp2f(m1 - mn1);

            uint32_t Ph[8][2];
            float sum0 = 0.f, sum1 = 0.f;
#pragma unroll
            for (int j = 0; j < 8; ++j) {
                float p0 = exp2f(s[j][0] - mn0);
                float p1 = exp2f(s[j][1] - mn0);
                float p2 = exp2f(s[j][2] - mn1);
                float p3 = exp2f(s[j][3] - mn1);
                sum0 += p0 + p1;
                sum1 += p2 + p3;
                Ph[j][0] = pack_f2(p0, p1);
                Ph[j][1] = pack_f2(p2, p3);
            }
            sum0 += __shfl_xor_sync(0xffffffffu, sum0, 1);
            sum0 += __shfl_xor_sync(0xffffffffu, sum0, 2);
            sum1 += __shfl_xor_sync(0xffffffffu, sum1, 1);
            sum1 += __shfl_xor_sync(0xffffffffu, sum1, 2);
            l0 = l0 * a0 + sum0;
            l1 = l1 * a1 + sum1;
            m0 = mn0; m1 = mn1;
#pragma unroll
            for (int j = 0; j < 8; ++j) {
                o[j][0] *= a0; o[j][1] *= a0; o[j][2] *= a1; o[j][3] *= a1;
            }

#pragma unroll
            for (int t = 0; t < 4; ++t) {
                uint32_t ap[4] = { Ph[2 * t][0], Ph[2 * t][1],
                                   Ph[2 * t + 1][0], Ph[2 * t + 1][1] };
                uint32_t vh[8][2];
                int vrow = t * 16 + (lane & 15);
#pragma unroll
                for (int g = 0; g < 4; ++g) {
                    uint32_t off = (uint32_t)(vrow * 144 + (g * 16 + (lane >> 4) * 8) * 2);
                    uint32_t r4[4];
                    ldsm_x4_t(r4, sVh + off);
                    vh[2 * g][0] = r4[0]; vh[2 * g][1] = r4[1];
                    vh[2 * g + 1][0] = r4[2]; vh[2 * g + 1][1] = r4[3];
                }
#pragma unroll
                for (int j = 0; j < 8; ++j)
                    mma_f16(o[j], ap, vh[j]);
            }
        }
        __syncthreads();
    }

    const float inv0 = 1.0f / l0, inv1 = 1.0f / l1;
    const int b = bh >> 4, h = bh & 15;
    const int s0 = q0w + (lane >> 2);
    const int c2 = 2 * (lane & 3);
#pragma unroll
    for (int j = 0; j < 8; ++j) {
        int dk = 8 * j + c2;
        {
            size_t idx = ((size_t)(b * S_) + s0) * D_ + h * 64 + dk;
            *(uint32_t*)(g_oh + idx) = pack_f2(o[j][0] * inv0, o[j][1] * inv0);
        }
        {
            size_t idx = ((size_t)(b * S_) + s0 + 8) * D_ + h * 64 + dk;
            *(uint32_t*)(g_oh + idx) = pack_f2(o[j][2] * inv1, o[j][3] * inv1);
        }
    }
}

// ---------------------------------------------------------------------------
// Launch
// ---------------------------------------------------------------------------
extern "C" void kernel_launch(void* const* d_in, const int* in_sizes, int n_in,
                              void* d_out, int out_size) {
    const float* x   = (const float*)d_in[0];
    const int*   pos = (const int*)d_in[1];
    const float* wq  = (const float*)d_in[2];
    const float* wk  = (const float*)d_in[3];
    const float* wv  = (const float*)d_in[4];
    const float* wo  = (const float*)d_in[5];
    float* out = (float*)d_out;
    (void)in_sizes; (void)n_in; (void)out_size;

    cudaFuncSetAttribute((const void*)qkv_gemm_kernel,
                         cudaFuncAttributeMaxDynamicSharedMemorySize, GEMM_SMEM);
    cudaFuncSetAttribute((const void*)out_gemm_kernel,
                         cudaFuncAttributeMaxDynamicSharedMemorySize, GEMM_SMEM);
    cudaFuncSetAttribute((const void*)attn_mma_kernel,
                         cudaFuncAttributeMaxDynamicSharedMemorySize, ATT_SMEM);

    // 1. Fused setup: RoPE table + fp16 converts (one launch)
    {
        int total = N_ROPE + N_CONV;
        setup_kernel<<<(total + 255) / 256, 256>>>(pos, x, wq, wk, wv, wo);
    }

    // 2. Fused QKV projection (z fastest-varying for L2 locality)
    qkv_gemm_kernel<<<dim3(3 * (D_ / 128), M_ / 128), 256, GEMM_SMEM>>>();

    // 3. fp16 tensor-core causal flash attention -> g_oh
    attn_mma_kernel<<<dim3(S_ / 128, B_ * H_), 256, ATT_SMEM>>>();

    // 4. Output projection -> d_out
    out_gemm_kernel<<<dim3(D_ / 128, M_ / 128), 256, GEMM_SMEM>>>(out);
}

// round 17
// speedup vs baseline: 1.1510x; 1.0256x over previous
#include <cuda_runtime.h>
#include <cuda_fp16.h>
#include <math.h>
#include <stdint.h>

#define B_  4
#define S_  2048
#define D_  1024
#define H_  16
#define DK_ 64
#define M_  (B_ * S_)

// ---------------------------------------------------------------------------
// Device-global scratch
// ---------------------------------------------------------------------------
__device__ float g_cos[S_ * 32];
__device__ float g_sin[S_ * 32];

__device__ __half g_xh[(size_t)M_ * D_];              // x single fp16
__device__ __half g_w[4][(size_t)D_ * D_];            // q,k,v,o single fp16
__device__ __half g_oh[(size_t)M_ * D_];              // O single fp16

// Q: single fp16 (pre-scaled 1/8 * log2e). K,V: single fp16.
__device__ __half g_Qh[(size_t)B_ * H_ * S_ * DK_];
__device__ __half g_Kh[(size_t)B_ * H_ * S_ * DK_];
__device__ __half g_Vh[(size_t)B_ * H_ * S_ * DK_];

// ---------------------------------------------------------------------------
// PTX helpers
// ---------------------------------------------------------------------------
__device__ __forceinline__ uint32_t smem_u32(const void* p) {
    uint32_t a;
    asm("{ .reg .u64 t; cvta.to.shared.u64 t, %1; cvt.u32.u64 %0, t; }"
        : "=r"(a) : "l"(p));
    return a;
}
__device__ __forceinline__ void ldsm_x4(uint32_t* r, uint32_t addr) {
    asm volatile("ldmatrix.sync.aligned.m8n8.x4.shared.b16 {%0,%1,%2,%3}, [%4];"
                 : "=r"(r[0]), "=r"(r[1]), "=r"(r[2]), "=r"(r[3]) : "r"(addr));
}
__device__ __forceinline__ void ldsm_x4_t(uint32_t* r, uint32_t addr) {
    asm volatile("ldmatrix.sync.aligned.m8n8.x4.trans.shared.b16 {%0,%1,%2,%3}, [%4];"
                 : "=r"(r[0]), "=r"(r[1]), "=r"(r[2]), "=r"(r[3]) : "r"(addr));
}
__device__ __forceinline__ void mma_f16(float* d, const uint32_t* a,
                                        const uint32_t* b) {
    asm volatile(
        "mma.sync.aligned.m16n8k16.row.col.f32.f16.f16.f32 "
        "{%0,%1,%2,%3}, {%4,%5,%6,%7}, {%8,%9}, {%0,%1,%2,%3};"
        : "+f"(d[0]), "+f"(d[1]), "+f"(d[2]), "+f"(d[3])
        : "r"(a[0]), "r"(a[1]), "r"(a[2]), "r"(a[3]), "r"(b[0]), "r"(b[1]));
}
__device__ __forceinline__ void cp16(uint32_t dst, const void* src) {
    asm volatile("cp.async.cg.shared.global [%0], [%1], 16;"
                 :: "r"(dst), "l"(src) : "memory");
}
#define CP_COMMIT() asm volatile("cp.async.commit_group;" ::: "memory")
#define CP_WAIT0()  asm volatile("cp.async.wait_group 0;" ::: "memory")
#define CP_WAIT1()  asm volatile("cp.async.wait_group 1;" ::: "memory")
#define CP_WAIT2()  asm volatile("cp.async.wait_group 2;" ::: "memory")

__device__ __forceinline__ uint32_t pack_f2(float a, float b) {
    __half2 v = __float22half2_rn(make_float2(a, b));
    return *(uint32_t*)&v;
}
__device__ __forceinline__ uint32_t ex2_h2(uint32_t x) {
    uint32_t r;
    asm("ex2.approx.f16x2 %0, %1;" : "=r"(r) : "r"(x));
    return r;
}

// ---------------------------------------------------------------------------
// Fused setup: RoPE table + x/weight fp16 converts in one launch.
// ---------------------------------------------------------------------------
#define N_ROPE   (S_ * 32)
#define N_CONV   (2097152 + 4 * 262144)

__global__ void setup_kernel(const int* __restrict__ pos,
                             const float* __restrict__ x,
                             const float* __restrict__ wq,
                             const float* __restrict__ wk,
                             const float* __restrict__ wv,
                             const float* __restrict__ wo) {
    int i = blockIdx.x * blockDim.x + threadIdx.x;
    if (i < N_ROPE) {
        int s = i >> 5;
        int p = i & 31;
        float inv_freq = (float)pow(10000.0, -((double)(2 * p)) / 64.0);
        float ang = (float)pos[s] * inv_freq;
        g_cos[i] = (float)cos((double)ang);
        g_sin[i] = (float)sin((double)ang);
        return;
    }
    int j = i - N_ROPE;
    if (j >= N_CONV) return;
    const float* src;
    __half* dst;
    int off;
    if (j < 2097152) {
        src = x; dst = g_xh; off = j;
    } else {
        int k = j - 2097152;
        int wsel = k >> 18;
        off = k & 262143;
        src = (wsel == 0) ? wq : (wsel == 1) ? wk : (wsel == 2) ? wv : wo;
        dst = g_w[wsel];
    }
    float4 v = ((const float4*)src)[off];
    ((uint32_t*)dst)[2 * off]     = pack_f2(v.x, v.y);
    ((uint32_t*)dst)[2 * off + 1] = pack_f2(v.z, v.w);
}

// ---------------------------------------------------------------------------
// Tile geometry shared by GEMMs (3-stage cp.async pipeline)
// ---------------------------------------------------------------------------
#define T_STRIDE 144
#define T_BYTES  (128 * T_STRIDE)        // 18432
#define G_STAGE  (2 * T_BYTES)           // 36864 (A, B)
#define GEMM_SMEM (3 * G_STAGE)          // 110592

// ---------------------------------------------------------------------------
// Fused QKV GEMM (fp16 single-term), z fastest-varying in blockIdx.x.
// ---------------------------------------------------------------------------
__global__ void __launch_bounds__(256, 2) qkv_gemm_kernel() {
    extern __shared__ char sm[];
    const int tid  = threadIdx.x;
    const int w    = tid >> 5;
    const int lane = tid & 31;
    const int wm   = w >> 1;
    const int wn   = w & 1;
    const int z    = blockIdx.x % 3;
    const int n0   = (blockIdx.x / 3) * 128;
    const int m0   = blockIdx.y * 128;

    const uint32_t sbase = smem_u32(sm);

    const __half* srcs[2] = {
        g_xh + (size_t)m0 * D_, g_w[z] + (size_t)n0 * D_ };

    auto load_stage = [&](int kt, int st) {
        uint32_t sb = sbase + st * G_STAGE;
#pragma unroll
        for (int t = 0; t < 2; ++t) {
#pragma unroll
            for (int u = 0; u < 4; ++u) {
                int f = tid + u * 256;
                int r = f >> 3;
                int c = f & 7;
                cp16(sb + t * T_BYTES + r * T_STRIDE + c * 16,
                     srcs[t] + (size_t)r * D_ + kt * 64 + c * 8);
            }
        }
    };

    float d[2][8][4];
#pragma unroll
    for (int i = 0; i < 2; ++i)
#pragma unroll
        for (int j = 0; j < 8; ++j)
#pragma unroll
            for (int q = 0; q < 4; ++q) d[i][j][q] = 0.f;

    load_stage(0, 0); CP_COMMIT();
    load_stage(1, 1); CP_COMMIT();

    int st = 0;
    for (int kt = 0; kt < 16; ++kt) {
        if (kt + 2 < 16) {
            load_stage(kt + 2, (st + 2) % 3);
            CP_COMMIT();
            CP_WAIT2();
        } else if (kt + 1 < 16) {
            CP_WAIT1();
        } else {
            CP_WAIT0();
        }
        __syncthreads();

        const uint32_t oA0 = sbase + st * G_STAGE;
        const uint32_t oB0 = oA0 + T_BYTES;

#pragma unroll
        for (int ks = 0; ks < 4; ++ks) {
            const int k0 = ks * 16;
            uint32_t ah[2][4];
            {
                int arow = wm * 32 + (lane & 15);
                int acol = 2 * k0 + (lane >> 4) * 16;
#pragma unroll
                for (int i = 0; i < 2; ++i) {
                    uint32_t off = (uint32_t)((arow + i * 16) * T_STRIDE + acol);
                    ldsm_x4(ah[i], oA0 + off);
                }
            }
            uint32_t bh[8][2];
            {
                int brow_l = (lane & 7) + ((lane >> 4) & 1) * 8;
                int bcol   = 2 * k0 + ((lane >> 3) & 1) * 16;
#pragma unroll
                for (int g = 0; g < 4; ++g) {
                    uint32_t off = (uint32_t)((wn * 64 + g * 16 + brow_l) * T_STRIDE + bcol);
                    uint32_t r4[4];
                    ldsm_x4(r4, oB0 + off);
                    bh[2 * g][0] = r4[0]; bh[2 * g][1] = r4[1];
                    bh[2 * g + 1][0] = r4[2]; bh[2 * g + 1][1] = r4[3];
                }
            }
#pragma unroll
            for (int i = 0; i < 2; ++i)
#pragma unroll
                for (int j = 0; j < 8; ++j)
                    mma_f16(d[i][j], ah[i], bh[j]);
        }
        __syncthreads();
        st = (st + 1) % 3;
    }

    // Epilogue: RoPE (z<2) + scatter to [b,h,s,dk]
    const float qscale = 0.125f * 1.44269504f;   // 1/sqrt(dk) * log2(e)
#pragma unroll
    for (int i = 0; i < 2; ++i) {
        int mrow = m0 + wm * 32 + i * 16 + (lane >> 2);
#pragma unroll
        for (int half = 0; half < 2; ++half) {
            int m = mrow + half * 8;
            int b = m >> 11;
            int s = m & (S_ - 1);
#pragma unroll
            for (int j = 0; j < 8; ++j) {
                int n = n0 + wn * 64 + j * 8 + 2 * (lane & 3);
                float x0 = d[i][j][2 * half];
                float x1 = d[i][j][2 * half + 1];
                int h = n >> 6;
                int dk = n & 63;
                float y0, y1;
                if (z != 2) {
                    int p = dk >> 1;
                    float c = g_cos[s * 32 + p];
                    float sn = g_sin[s * 32 + p];
                    y0 = c * x0 - sn * x1;
                    y1 = sn * x0 + c * x1;
                } else {
                    y0 = x0; y1 = x1;
                }
                if (z == 0) { y0 *= qscale; y1 *= qscale; }
                size_t idx = (((size_t)(b * H_ + h) * S_ + s) * DK_ + dk);
                uint32_t pk = pack_f2(y0, y1);
                if (z == 0)      *(uint32_t*)(g_Qh + idx) = pk;
                else if (z == 1) *(uint32_t*)(g_Kh + idx) = pk;
                else             *(uint32_t*)(g_Vh + idx) = pk;
            }
        }
    }
}

// ---------------------------------------------------------------------------
// Output projection GEMM (fp16 single-term): out = O Wo^T, fp32 store.
// ---------------------------------------------------------------------------
__global__ void __launch_bounds__(256, 2) out_gemm_kernel(float* __restrict__ Cout) {
    extern __shared__ char sm[];
    const int tid  = threadIdx.x;
    const int w    = tid >> 5;
    const int lane = tid & 31;
    const int wm   = w >> 1;
    const int wn   = w & 1;
    const int n0   = blockIdx.x * 128;
    const int m0   = blockIdx.y * 128;

    const uint32_t sbase = smem_u32(sm);

    const __half* srcs[2] = {
        g_oh + (size_t)m0 * D_, g_w[3] + (size_t)n0 * D_ };

    auto load_stage = [&](int kt, int st) {
        uint32_t sb = sbase + st * G_STAGE;
#pragma unroll
        for (int t = 0; t < 2; ++t) {
#pragma unroll
            for (int u = 0; u < 4; ++u) {
                int f = tid + u * 256;
                int r = f >> 3;
                int c = f & 7;
                cp16(sb + t * T_BYTES + r * T_STRIDE + c * 16,
                     srcs[t] + (size_t)r * D_ + kt * 64 + c * 8);
            }
        }
    };

    float d[2][8][4];
#pragma unroll
    for (int i = 0; i < 2; ++i)
#pragma unroll
        for (int j = 0; j < 8; ++j)
#pragma unroll
            for (int q = 0; q < 4; ++q) d[i][j][q] = 0.f;

    load_stage(0, 0); CP_COMMIT();
    load_stage(1, 1); CP_COMMIT();

    int st = 0;
    for (int kt = 0; kt < 16; ++kt) {
        if (kt + 2 < 16) {
            load_stage(kt + 2, (st + 2) % 3);
            CP_COMMIT();
            CP_WAIT2();
        } else if (kt + 1 < 16) {
            CP_WAIT1();
        } else {
            CP_WAIT0();
        }
        __syncthreads();

        const uint32_t oA0 = sbase + st * G_STAGE;
        const uint32_t oB0 = oA0 + T_BYTES;

#pragma unroll
        for (int ks = 0; ks < 4; ++ks) {
            const int k0 = ks * 16;
            uint32_t ah[2][4];
            {
                int arow = wm * 32 + (lane & 15);
                int acol = 2 * k0 + (lane >> 4) * 16;
#pragma unroll
                for (int i = 0; i < 2; ++i) {
                    uint32_t off = (uint32_t)((arow + i * 16) * T_STRIDE + acol);
                    ldsm_x4(ah[i], oA0 + off);
                }
            }
            uint32_t bh[8][2];
            {
                int brow_l = (lane & 7) + ((lane >> 4) & 1) * 8;
                int bcol   = 2 * k0 + ((lane >> 3) & 1) * 16;
#pragma unroll
                for (int g = 0; g < 4; ++g) {
                    uint32_t off = (uint32_t)((wn * 64 + g * 16 + brow_l) * T_STRIDE + bcol);
                    uint32_t r4[4];
                    ldsm_x4(r4, oB0 + off);
                    bh[2 * g][0] = r4[0]; bh[2 * g][1] = r4[1];
                    bh[2 * g + 1][0] = r4[2]; bh[2 * g + 1][1] = r4[3];
                }
            }
#pragma unroll
            for (int i = 0; i < 2; ++i)
#pragma unroll
                for (int j = 0; j < 8; ++j)
                    mma_f16(d[i][j], ah[i], bh[j]);
        }
        __syncthreads();
        st = (st + 1) % 3;
    }

#pragma unroll
    for (int i = 0; i < 2; ++i) {
        int mrow = m0 + wm * 32 + i * 16 + (lane >> 2);
#pragma unroll
        for (int half = 0; half < 2; ++half) {
            int m = mrow + half * 8;
#pragma unroll
            for (int j = 0; j < 8; ++j) {
                int n = n0 + wn * 64 + j * 8 + 2 * (lane & 3);
                *(float2*)(Cout + (size_t)m * D_ + n) =
                    make_float2(d[i][j][2 * half], d[i][j][2 * half + 1]);
            }
        }
    }
}

// ---------------------------------------------------------------------------
// Tensor-core flash attention (causal, fp16, exp2-domain softmax):
// 128-key load stages, two 64-key halves; P via ex2.approx.f16x2;
// row-sums l via ones-fragment MMA (normalization-consistent).
// ---------------------------------------------------------------------------
#define AK_TILE (128 * 144)               // 18432 (128 rows)
#define A_STAGE (2 * AK_TILE)             // 36864 (K128, V128)
#define ATT_SMEM (2 * A_STAGE)            // 73728

__global__ void __launch_bounds__(256, 2) attn_mma_kernel() {
    extern __shared__ char asm_[];
    const int qb = gridDim.x - 1 - blockIdx.x;
    const int bh = blockIdx.y;
    const int tid = threadIdx.x;
    const int w = tid >> 5;
    const int lane = tid & 31;
    const int q0w = qb * 128 + w * 16;
    const size_t hb = (size_t)bh * S_ * DK_;

    const uint32_t sbase = smem_u32(asm_);

    const __half* srcs[2] = { g_Kh + hb, g_Vh + hb };

    auto load_stage = [&](int kt, int st) {
        uint32_t sb = sbase + st * A_STAGE;
        const size_t roff = (size_t)(kt * 128) * 64;
#pragma unroll
        for (int t = 0; t < 2; ++t) {
#pragma unroll
            for (int u = 0; u < 4; ++u) {
                int f = tid + u * 256;
                int r = f >> 3;
                int c = f & 7;
                cp16(sb + t * AK_TILE + r * 144 + c * 16,
                     srcs[t] + roff + (size_t)r * 64 + c * 8);
            }
        }
    };

    uint32_t qh[4][4];
    {
        const int r0 = q0w + (lane >> 2);
        const int c2 = (lane & 3) * 2;
        const __half* Qh = g_Qh + hb;
#pragma unroll
        for (int t = 0; t < 4; ++t) {
            qh[t][0] = *(const uint32_t*)(Qh + (size_t)r0 * 64 + t * 16 + c2);
            qh[t][1] = *(const uint32_t*)(Qh + (size_t)(r0 + 8) * 64 + t * 16 + c2);
            qh[t][2] = *(const uint32_t*)(Qh + (size_t)r0 * 64 + t * 16 + 8 + c2);
            qh[t][3] = *(const uint32_t*)(Qh + (size_t)(r0 + 8) * 64 + t * 16 + 8 + c2);
        }
    }

    float o[8][4];
#pragma unroll
    for (int j = 0; j < 8; ++j)
#pragma unroll
        for (int q = 0; q < 4; ++q) o[j][q] = 0.f;
    float m0 = -3.0e38f, m1 = -3.0e38f, l0 = 0.f, l1 = 0.f;

    const uint32_t ones_b[2] = { 0x3C003C00u, 0x3C003C00u };  // half2(1,1)

    const int nkt = qb + 1;
    load_stage(0, 0);
    CP_COMMIT();

    for (int kt = 0; kt < nkt; ++kt) {
        const int st = kt & 1;
        if (kt + 1 < nkt) {
            load_stage(kt + 1, st ^ 1);
            CP_COMMIT();
            CP_WAIT1();
        } else {
            CP_WAIT0();
        }
        __syncthreads();

#pragma unroll
        for (int hh = 0; hh < 2; ++hh) {
            const int k0 = kt * 128 + hh * 64;
            if (q0w + 15 < k0) break;

            const uint32_t sKh = sbase + st * A_STAGE + hh * (64 * 144);
            const uint32_t sVh = sbase + st * A_STAGE + AK_TILE + hh * (64 * 144);

            // ---- S(log2) = Q * K^T ----
            float s[8][4];
#pragma unroll
            for (int j = 0; j < 8; ++j)
#pragma unroll
                for (int q = 0; q < 4; ++q) s[j][q] = 0.f;

            const int brow = (lane & 7) + ((lane >> 4) & 1) * 8;
#pragma unroll
            for (int t = 0; t < 4; ++t) {
                uint32_t kh[8][2];
                int bcol = t * 32 + ((lane >> 3) & 1) * 16;
#pragma unroll
                for (int g = 0; g < 4; ++g) {
                    uint32_t off = (uint32_t)((g * 16 + brow) * 144 + bcol);
                    uint32_t r4[4];
                    ldsm_x4(r4, sKh + off);
                    kh[2 * g][0] = r4[0]; kh[2 * g][1] = r4[1];
                    kh[2 * g + 1][0] = r4[2]; kh[2 * g + 1][1] = r4[3];
                }
#pragma unroll
                for (int j = 0; j < 8; ++j)
                    mma_f16(s[j], qh[t], kh[j]);
            }

            // ---- causal mask ----
            const int r0 = q0w + (lane >> 2);
            if (k0 + 63 > q0w) {
#pragma unroll
                for (int j = 0; j < 8; ++j) {
                    int col = k0 + 8 * j + 2 * (lane & 3);
                    if (col > r0)         s[j][0] = -3.0e38f;
                    if (col + 1 > r0)     s[j][1] = -3.0e38f;
                    if (col > r0 + 8)     s[j][2] = -3.0e38f;
                    if (col + 1 > r0 + 8) s[j][3] = -3.0e38f;
                }
            }

            // ---- online softmax: max, then P = ex2.f16x2(s - m) ----
            float mx0 = -3.0e38f, mx1 = -3.0e38f;
#pragma unroll
            for (int j = 0; j < 8; ++j) {
                mx0 = fmaxf(mx0, fmaxf(s[j][0], s[j][1]));
                mx1 = fmaxf(mx1, fmaxf(s[j][2], s[j][3]));
            }
            mx0 = fmaxf(mx0, __shfl_xor_sync(0xffffffffu, mx0, 1));
            mx0 = fmaxf(mx0, __shfl_xor_sync(0xffffffffu, mx0, 2));
            mx1 = fmaxf(mx1, __shfl_xor_sync(0xffffffffu, mx1, 1));
            mx1 = fmaxf(mx1, __shfl_xor_sync(0xffffffffu, mx1, 2));
            float mn0 = fmaxf(m0, mx0), mn1 = fmaxf(m1, mx1);
            float a0 = exp2f(m0 - mn0), a1 = exp2f(m1 - mn1);

            uint32_t Ph[8][2];
#pragma unroll
            for (int j = 0; j < 8; ++j) {
                Ph[j][0] = ex2_h2(pack_f2(s[j][0] - mn0, s[j][1] - mn0));
                Ph[j][1] = ex2_h2(pack_f2(s[j][2] - mn1, s[j][3] - mn1));
            }
            m0 = mn0; m1 = mn1;
#pragma unroll
            for (int j = 0; j < 8; ++j) {
                o[j][0] *= a0; o[j][1] *= a0; o[j][2] *= a1; o[j][3] *= a1;
            }

            // ---- O += P * V; row-sums via ones-MMA ----
            float lacc[4] = { 0.f, 0.f, 0.f, 0.f };
#pragma unroll
            for (int t = 0; t < 4; ++t) {
                uint32_t ap[4] = { Ph[2 * t][0], Ph[2 * t][1],
                                   Ph[2 * t + 1][0], Ph[2 * t + 1][1] };
                uint32_t vh[8][2];
                int vrow = t * 16 + (lane & 15);
#pragma unroll
                for (int g = 0; g < 4; ++g) {
                    uint32_t off = (uint32_t)(vrow * 144 + (g * 16 + (lane >> 4) * 8) * 2);
                    uint32_t r4[4];
                    ldsm_x4_t(r4, sVh + off);
                    vh[2 * g][0] = r4[0]; vh[2 * g][1] = r4[1];
                    vh[2 * g + 1][0] = r4[2]; vh[2 * g + 1][1] = r4[3];
                }
                mma_f16(lacc, ap, ones_b);
#pragma unroll
                for (int j = 0; j < 8; ++j)
                    mma_f16(o[j], ap, vh[j]);
            }
            l0 = l0 * a0 + lacc[0];
            l1 = l1 * a1 + lacc[2];
        }
        __syncthreads();
    }

    // ---- epilogue: normalize, write single fp16 O in [b,s,h*dk] ----
    const float inv0 = 1.0f / l0, inv1 = 1.0f / l1;
    const int b = bh >> 4, h = bh & 15;
    const int s0 = q0w + (lane >> 2);
    const int c2 = 2 * (lane & 3);
#pragma unroll
    for (int j = 0; j < 8; ++j) {
        int dk = 8 * j + c2;
        {
            size_t idx = ((size_t)(b * S_) + s0) * D_ + h * 64 + dk;
            *(uint32_t*)(g_oh + idx) = pack_f2(o[j][0] * inv0, o[j][1] * inv0);
        }
        {
            size_t idx = ((size_t)(b * S_) + s0 + 8) * D_ + h * 64 + dk;
            *(uint32_t*)(g_oh + idx) = pack_f2(o[j][2] * inv1, o[j][3] * inv1);
        }
    }
}

// ---------------------------------------------------------------------------
// Launch
// ---------------------------------------------------------------------------
extern "C" void kernel_launch(void* const* d_in, const int* in_sizes, int n_in,
                              void* d_out, int out_size) {
    const float* x   = (const float*)d_in[0];
    const int*   pos = (const int*)d_in[1];
    const float* wq  = (const float*)d_in[2];
    const float* wk  = (const float*)d_in[3];
    const float* wv  = (const float*)d_in[4];
    const float* wo  = (const float*)d_in[5];
    float* out = (float*)d_out;
    (void)in_sizes; (void)n_in; (void)out_size;

    cudaFuncSetAttribute((const void*)qkv_gemm_kernel,
                         cudaFuncAttributeMaxDynamicSharedMemorySize, GEMM_SMEM);
    cudaFuncSetAttribute((const void*)out_gemm_kernel,
                         cudaFuncAttributeMaxDynamicSharedMemorySize, GEMM_SMEM);
    cudaFuncSetAttribute((const void*)attn_mma_kernel,
                         cudaFuncAttributeMaxDynamicSharedMemorySize, ATT_SMEM);

    // 1. Fused setup: RoPE table + fp16 converts
    {
        int total = N_ROPE + N_CONV;
        setup_kernel<<<(total + 255) / 256, 256>>>(pos, x, wq, wk, wv, wo);
    }

    // 2. Fused QKV projection (z fastest-varying for L2 locality)
    qkv_gemm_kernel<<<dim3(3 * (D_ / 128), M_ / 128), 256, GEMM_SMEM>>>();

    // 3. fp16 tensor-core causal flash attention -> g_oh
    attn_mma_kernel<<<dim3(S_ / 128, B_ * H_), 256, ATT_SMEM>>>();

    // 4. Output projection -> d_out
    out_gemm_kernel<<<dim3(D_ / 128, M_ / 128), 256, GEMM_SMEM>>>(out);
}